// round 15
// baseline (speedup 1.0000x reference)
#include <cuda_runtime.h>
#include <cuda_bf16.h>
#include <math.h>
#include <stdint.h>

// Problem shapes (fixed)
#define BB 64
#define TT 512
#define DD 1024
#define UU 128
#define MM (BB * TT)

typedef unsigned long long u64;

// Scratch (no cudaMalloc allowed)
__device__ float g_logits[MM * UU];   // GEMM output
__device__ float g_hist[MM * UU];     // viterbi state history (t>=1)
__device__ int   g_flags[4 * BB];     // per (chunk, batch) ready flags

__global__ void reset_kernel()
{
    g_flags[threadIdx.x] = 0;
}

// ---------------------------------------------------------------------------
// Kernel 1: logits = X @ W + bias, chunk-major tiles, publishes ready flags.
// Tile BM=128 (= one 128-step t-chunk of one batch), BN=128, BK=16,
// double-buffered, 256 threads, 8x8 accum. Exact fp32.
// ---------------------------------------------------------------------------
#define GBM 128
#define GBK 16

__global__ __launch_bounds__(256, 2)
void gemm_bias_kernel(const float* __restrict__ A,
                      const float* __restrict__ W,
                      const float* __restrict__ bias)
{
    __shared__ float As[2][GBK][GBM];
    __shared__ float Bs[2][GBK][UU];

    const int tid   = threadIdx.x;
    const int chunk = blockIdx.x >> 6;      // 0..3
    const int batch = blockIdx.x & 63;      // 0..63
    const int row0  = batch * TT + chunk * 128;

    const int arow = tid >> 2;
    const int ak   = (tid & 3) * 4;
    const int wk   = tid >> 5;
    const int wcol = (tid & 31) * 4;

    const int tx = tid & 15;
    const int ty = tid >> 4;

    float acc[8][8];
    #pragma unroll
    for (int i = 0; i < 8; i++)
        #pragma unroll
        for (int j = 0; j < 8; j++)
            acc[i][j] = 0.0f;

    const float* A0 = A + (size_t)(row0 + arow) * DD + ak;
    const float* A1 = A + (size_t)(row0 + arow + 64) * DD + ak;

    float4 ra0 = *reinterpret_cast<const float4*>(A0);
    float4 ra1 = *reinterpret_cast<const float4*>(A1);
    float4 rw0 = *reinterpret_cast<const float4*>(&W[(size_t)wk * UU + wcol]);
    float4 rw1 = *reinterpret_cast<const float4*>(&W[(size_t)(wk + 8) * UU + wcol]);

    As[0][ak + 0][arow] = ra0.x; As[0][ak + 1][arow] = ra0.y;
    As[0][ak + 2][arow] = ra0.z; As[0][ak + 3][arow] = ra0.w;
    As[0][ak + 0][arow + 64] = ra1.x; As[0][ak + 1][arow + 64] = ra1.y;
    As[0][ak + 2][arow + 64] = ra1.z; As[0][ak + 3][arow + 64] = ra1.w;
    *reinterpret_cast<float4*>(&Bs[0][wk][wcol])     = rw0;
    *reinterpret_cast<float4*>(&Bs[0][wk + 8][wcol]) = rw1;
    __syncthreads();

    int st = 0;
    for (int k0 = GBK; k0 <= DD; k0 += GBK) {
        const bool more = (k0 < DD);
        if (more) {
            ra0 = *reinterpret_cast<const float4*>(A0 + k0);
            ra1 = *reinterpret_cast<const float4*>(A1 + k0);
            rw0 = *reinterpret_cast<const float4*>(&W[(size_t)(k0 + wk) * UU + wcol]);
            rw1 = *reinterpret_cast<const float4*>(&W[(size_t)(k0 + wk + 8) * UU + wcol]);
        }

        #pragma unroll
        for (int k = 0; k < GBK; k++) {
            float a[8], b[8];
            *reinterpret_cast<float4*>(&a[0]) =
                *reinterpret_cast<const float4*>(&As[st][k][ty * 8]);
            *reinterpret_cast<float4*>(&a[4]) =
                *reinterpret_cast<const float4*>(&As[st][k][ty * 8 + 4]);
            *reinterpret_cast<float4*>(&b[0]) =
                *reinterpret_cast<const float4*>(&Bs[st][k][tx * 8]);
            *reinterpret_cast<float4*>(&b[4]) =
                *reinterpret_cast<const float4*>(&Bs[st][k][tx * 8 + 4]);
            #pragma unroll
            for (int i = 0; i < 8; i++)
                #pragma unroll
                for (int j = 0; j < 8; j++)
                    acc[i][j] = fmaf(a[i], b[j], acc[i][j]);
        }

        if (more) {
            const int ns = st ^ 1;
            As[ns][ak + 0][arow] = ra0.x; As[ns][ak + 1][arow] = ra0.y;
            As[ns][ak + 2][arow] = ra0.z; As[ns][ak + 3][arow] = ra0.w;
            As[ns][ak + 0][arow + 64] = ra1.x; As[ns][ak + 1][arow + 64] = ra1.y;
            As[ns][ak + 2][arow + 64] = ra1.z; As[ns][ak + 3][arow + 64] = ra1.w;
            *reinterpret_cast<float4*>(&Bs[ns][wk][wcol])     = rw0;
            *reinterpret_cast<float4*>(&Bs[ns][wk + 8][wcol]) = rw1;
            __syncthreads();
            st = ns;
        }
    }

    float bv[8];
    *reinterpret_cast<float4*>(&bv[0]) =
        *reinterpret_cast<const float4*>(&bias[tx * 8]);
    *reinterpret_cast<float4*>(&bv[4]) =
        *reinterpret_cast<const float4*>(&bias[tx * 8 + 4]);

    #pragma unroll
    for (int i = 0; i < 8; i++) {
        const size_t row = (size_t)(row0 + ty * 8 + i);
        float4 o0, o1;
        o0.x = acc[i][0] + bv[0]; o0.y = acc[i][1] + bv[1];
        o0.z = acc[i][2] + bv[2]; o0.w = acc[i][3] + bv[3];
        o1.x = acc[i][4] + bv[4]; o1.y = acc[i][5] + bv[5];
        o1.z = acc[i][6] + bv[6]; o1.w = acc[i][7] + bv[7];
        *reinterpret_cast<float4*>(&g_logits[row * UU + tx * 8])     = o0;
        *reinterpret_cast<float4*>(&g_logits[row * UU + tx * 8 + 4]) = o1;
    }

    // publish
    __threadfence();
    __syncthreads();
    if (tid == 0)
        atomicExch(&g_flags[chunk * 64 + batch], 1);
}

// ---------------------------------------------------------------------------
// ordered-int argmax helpers (exact, first-index tie rule)
// ---------------------------------------------------------------------------
__device__ __forceinline__ unsigned fkey(float f)
{
    const unsigned b = __float_as_uint(f);
    return b ^ ((unsigned)(((int)b) >> 31) | 0x80000000u);
}
__device__ __forceinline__ unsigned redux_max_u32(unsigned v)
{
    unsigned r;
    asm("redux.sync.max.u32 %0, %1, 0xffffffff;" : "=r"(r) : "r"(v));
    return r;
}
__device__ __forceinline__ unsigned redux_min_u32(unsigned v)
{
    unsigned r;
    asm("redux.sync.min.u32 %0, %1, 0xffffffff;" : "=r"(r) : "r"(v));
    return r;
}

// packed fp32 helpers (Blackwell f32x2)
#define ADD2(d, a, b) \
    asm("add.rn.f32x2 %0, %1, %2;" : "=l"(d) : "l"(a), "l"(b))
#define UNPK2(lo, hi, v) \
    asm("mov.b64 {%0, %1}, %2;" : "=r"(lo), "=r"(hi) : "l"(v))

// ---------------------------------------------------------------------------
// Kernel 2: Viterbi consumer. One CTA/batch, 128 threads, thread = state u.
// Waits on g_flags at 128-step chunk boundaries; otherwise identical to the
// proven R13 structure (packed ADD2 + 16 scalar max accumulators, broadcast
// LDS, one barrier/step). 1-ahead pot prefetch with boundary reload.
// ---------------------------------------------------------------------------
#define CHT_LD 132   // 528B rows: 16B-aligned, de-striped STS

__global__ __launch_bounds__(128, 1)
void viterbi_kernel(const float* __restrict__ chain,
                    float* __restrict__ out)
{
    extern __shared__ float sm[];
    float* chT   = sm;                 // [128][CHT_LD]
    float* state = sm + UU * CHT_LD;   // [2][128]

    const int tid = threadIdx.x;       // = u, 0..127
    const int b   = blockIdx.x;
    const int u   = tid;

    const float* lg = g_logits + (size_t)b * TT * UU;
    float*       hb = g_hist   + (size_t)b * TT * UU;

    // Work independent of logits first (overlaps with producer):
    for (int i = tid; i < UU * UU; i += 128) {
        const int r = i >> 7, c = i & 127;
        chT[c * CHT_LD + r] = chain[i];
    }

    u64 cpk[64];
    #pragma unroll
    for (int k = 0; k < 64; k++) {
        const float c0 = chain[(size_t)(2 * k)     * UU + u];
        const float c1 = chain[(size_t)(2 * k + 1) * UU + u];
        asm("mov.b64 %0, {%1, %2};" : "=l"(cpk[k])
            : "r"(__float_as_uint(c0)), "r"(__float_as_uint(c1)));
    }

    // Wait for chunk 0 of this batch.
    if (tid == 0)
        while (*(volatile int*)&g_flags[b] == 0) { }
    __syncthreads();
    __threadfence();

    state[tid] = lg[tid];
    float potbuf = lg[UU + u];
    float* hist_ptr = hb + (size_t)1 * UU + u;
    __syncthreads();

    int cur = 0;
    for (int t = 1; t < TT; t++) {
        float pot;
        if ((t & 127) == 0) {
            // chunk boundary: wait for producer, then load fresh
            if (tid == 0)
                while (*(volatile int*)&g_flags[(t >> 7) * 64 + b] == 0) { }
            __syncthreads();
            __threadfence();
            pot = lg[(size_t)t * UU + u];
        } else {
            pot = potbuf;
        }
        if (t + 1 < TT && ((t + 1) & 127) != 0)
            potbuf = lg[(size_t)(t + 1) * UU + u];

        const float* stp = state + cur * UU;

        float ma0 = -INFINITY, ma1 = -INFINITY, ma2 = -INFINITY,
              ma3 = -INFINITY, ma4 = -INFINITY, ma5 = -INFINITY,
              ma6 = -INFINITY, ma7 = -INFINITY;
        float mb0 = -INFINITY, mb1 = -INFINITY, mb2 = -INFINITY,
              mb3 = -INFINITY, mb4 = -INFINITY, mb5 = -INFINITY,
              mb6 = -INFINITY, mb7 = -INFINITY;
        #pragma unroll
        for (int j = 0; j < 128; j += 16) {
            const ulonglong2 sA =
                *reinterpret_cast<const ulonglong2*>(&stp[j]);
            const ulonglong2 sB =
                *reinterpret_cast<const ulonglong2*>(&stp[j + 4]);
            const ulonglong2 sC =
                *reinterpret_cast<const ulonglong2*>(&stp[j + 8]);
            const ulonglong2 sD =
                *reinterpret_cast<const ulonglong2*>(&stp[j + 12]);
            u64 r0, r1, r2, r3, r4, r5, r6, r7;
            ADD2(r0, sA.x, cpk[(j >> 1) + 0]);
            ADD2(r1, sA.y, cpk[(j >> 1) + 1]);
            ADD2(r2, sB.x, cpk[(j >> 1) + 2]);
            ADD2(r3, sB.y, cpk[(j >> 1) + 3]);
            ADD2(r4, sC.x, cpk[(j >> 1) + 4]);
            ADD2(r5, sC.y, cpk[(j >> 1) + 5]);
            ADD2(r6, sD.x, cpk[(j >> 1) + 6]);
            ADD2(r7, sD.y, cpk[(j >> 1) + 7]);
            unsigned x0, x1, x2, x3, x4, x5, x6, x7;
            unsigned y0, y1, y2, y3, y4, y5, y6, y7;
            UNPK2(x0, x1, r0);
            UNPK2(x2, x3, r1);
            UNPK2(x4, x5, r2);
            UNPK2(x6, x7, r3);
            UNPK2(y0, y1, r4);
            UNPK2(y2, y3, r5);
            UNPK2(y4, y5, r6);
            UNPK2(y6, y7, r7);
            ma0 = fmaxf(ma0, __uint_as_float(x0));
            ma1 = fmaxf(ma1, __uint_as_float(x1));
            ma2 = fmaxf(ma2, __uint_as_float(x2));
            ma3 = fmaxf(ma3, __uint_as_float(x3));
            ma4 = fmaxf(ma4, __uint_as_float(x4));
            ma5 = fmaxf(ma5, __uint_as_float(x5));
            ma6 = fmaxf(ma6, __uint_as_float(x6));
            ma7 = fmaxf(ma7, __uint_as_float(x7));
            mb0 = fmaxf(mb0, __uint_as_float(y0));
            mb1 = fmaxf(mb1, __uint_as_float(y1));
            mb2 = fmaxf(mb2, __uint_as_float(y2));
            mb3 = fmaxf(mb3, __uint_as_float(y3));
            mb4 = fmaxf(mb4, __uint_as_float(y4));
            mb5 = fmaxf(mb5, __uint_as_float(y5));
            mb6 = fmaxf(mb6, __uint_as_float(y6));
            mb7 = fmaxf(mb7, __uint_as_float(y7));
        }
        const float mA = fmaxf(fmaxf(fmaxf(ma0, ma1), fmaxf(ma2, ma3)),
                               fmaxf(fmaxf(ma4, ma5), fmaxf(ma6, ma7)));
        const float mB = fmaxf(fmaxf(fmaxf(mb0, mb1), fmaxf(mb2, mb3)),
                               fmaxf(fmaxf(mb4, mb5), fmaxf(mb6, mb7)));
        const float ns = pot + fmaxf(mA, mB);
        state[(cur ^ 1) * UU + u] = ns;
        *hist_ptr = ns;
        hist_ptr += UU;
        cur ^= 1;
        __syncthreads();
    }

    // ---------------- Backtrace: warp 0 only ----------------
    if (tid < 32) {
        const int lane = tid;
        float* o = out + (size_t)b * TT;

        const float4 fs =
            *reinterpret_cast<const float4*>(&state[cur * UU + lane * 4]);
        unsigned k0 = fkey(fs.x), k1 = fkey(fs.y);
        unsigned k2 = fkey(fs.z), k3 = fkey(fs.w);
        unsigned M = redux_max_u32(umax(umax(k0, k1), umax(k2, k3)));
        unsigned idx = 0x7fffffffu;
        if (k3 == M) idx = lane * 4 + 3;
        if (k2 == M) idx = lane * 4 + 2;
        if (k1 == M) idx = lane * 4 + 1;
        if (k0 == M) idx = lane * 4 + 0;
        unsigned tag = redux_min_u32(idx);
        if (lane == 0) o[TT - 1] = (float)tag;

        const float* row_next = hb + (size_t)(TT - 2) * UU;
        float4 sb = *reinterpret_cast<const float4*>(&row_next[lane * 4]);
        for (int tt = TT - 2; tt >= 0; tt--) {
            const float4 sv = sb;
            if (tt > 0) {
                const float* rp =
                    (tt - 1 == 0) ? lg : hb + (size_t)(tt - 1) * UU;
                sb = *reinterpret_cast<const float4*>(&rp[lane * 4]);
            }
            const float4 ch = *reinterpret_cast<const float4*>(
                &chT[tag * CHT_LD + lane * 4]);
            k0 = fkey(sv.x + ch.x);
            k1 = fkey(sv.y + ch.y);
            k2 = fkey(sv.z + ch.z);
            k3 = fkey(sv.w + ch.w);
            M = redux_max_u32(umax(umax(k0, k1), umax(k2, k3)));
            idx = 0x7fffffffu;
            if (k3 == M) idx = lane * 4 + 3;
            if (k2 == M) idx = lane * 4 + 2;
            if (k1 == M) idx = lane * 4 + 1;
            if (k0 == M) idx = lane * 4 + 0;
            tag = redux_min_u32(idx);
            if (lane == 0) o[tt] = (float)tag;
        }
    }
}

// ---------------------------------------------------------------------------
// Launch: reset -> fork {GEMM on stream 0, Viterbi on s2} -> join.
// Multi-stream fork/join via events is the documented graph-capture pattern.
// GEMM never waits => no deadlock; viterbi streams one chunk behind.
// ---------------------------------------------------------------------------
extern "C" void kernel_launch(void* const* d_in, const int* in_sizes, int n_in,
                              void* d_out, int out_size)
{
    const float* inputs = (const float*)d_in[0];   // (B,T,D)
    const float* kernel = (const float*)d_in[1];   // (D,U)
    const float* bias   = (const float*)d_in[2];   // (U)
    const float* chain  = (const float*)d_in[3];   // (U,U)
    float* out = (float*)d_out;                    // (B,T)

    (void)in_sizes; (void)n_in; (void)out_size;

    const int smem_v = (UU * CHT_LD + 2 * UU) * (int)sizeof(float); // 68608
    cudaFuncSetAttribute(viterbi_kernel,
                         cudaFuncAttributeMaxDynamicSharedMemorySize,
                         smem_v);

    cudaStream_t s2;
    cudaStreamCreateWithFlags(&s2, cudaStreamNonBlocking);
    cudaEvent_t e1, e2;
    cudaEventCreateWithFlags(&e1, cudaEventDisableTiming);
    cudaEventCreateWithFlags(&e2, cudaEventDisableTiming);

    // reset flags (must precede both branches)
    reset_kernel<<<1, 4 * BB>>>();

    // fork
    cudaEventRecord(e1, 0);
    cudaStreamWaitEvent(s2, e1, 0);

    // producer on stream 0, consumer on s2 (concurrent graph branches)
    gemm_bias_kernel<<<4 * BB, 256>>>(inputs, kernel, bias);
    viterbi_kernel<<<BB, 128, smem_v, s2>>>(chain, out);

    // join
    cudaEventRecord(e2, s2);
    cudaStreamWaitEvent(0, e2, 0);
}

// round 16
// speedup vs baseline: 1.1482x; 1.1482x over previous
#include <cuda_runtime.h>
#include <cuda_bf16.h>
#include <math.h>
#include <stdint.h>

// Problem shapes (fixed)
#define BB 64
#define TT 512
#define DD 1024
#define UU 128
#define MM (BB * TT)

typedef unsigned long long u64;

// Scratch (no cudaMalloc allowed)
__device__ float g_logits[MM * UU];   // GEMM output
__device__ float g_hist[MM * UU];     // viterbi state history (t>=1)

// ---------------------------------------------------------------------------
// Kernel 1: logits = X(M,K) @ W(K,U) + bias  (exact fp32, double-buffered)
// ---------------------------------------------------------------------------
#define GBM 128
#define GBK 16

__global__ __launch_bounds__(256, 2)
void gemm_bias_kernel(const float* __restrict__ A,
                      const float* __restrict__ W,
                      const float* __restrict__ bias)
{
    __shared__ float As[2][GBK][GBM];
    __shared__ float Bs[2][GBK][UU];

    const int tid  = threadIdx.x;
    const int row0 = blockIdx.x * GBM;

    const int arow = tid >> 2;
    const int ak   = (tid & 3) * 4;
    const int wk   = tid >> 5;
    const int wcol = (tid & 31) * 4;

    const int tx = tid & 15;
    const int ty = tid >> 4;

    float acc[8][8];
    #pragma unroll
    for (int i = 0; i < 8; i++)
        #pragma unroll
        for (int j = 0; j < 8; j++)
            acc[i][j] = 0.0f;

    const float* A0 = A + (size_t)(row0 + arow) * DD + ak;
    const float* A1 = A + (size_t)(row0 + arow + 64) * DD + ak;

    float4 ra0 = *reinterpret_cast<const float4*>(A0);
    float4 ra1 = *reinterpret_cast<const float4*>(A1);
    float4 rw0 = *reinterpret_cast<const float4*>(&W[(size_t)wk * UU + wcol]);
    float4 rw1 = *reinterpret_cast<const float4*>(&W[(size_t)(wk + 8) * UU + wcol]);

    As[0][ak + 0][arow] = ra0.x; As[0][ak + 1][arow] = ra0.y;
    As[0][ak + 2][arow] = ra0.z; As[0][ak + 3][arow] = ra0.w;
    As[0][ak + 0][arow + 64] = ra1.x; As[0][ak + 1][arow + 64] = ra1.y;
    As[0][ak + 2][arow + 64] = ra1.z; As[0][ak + 3][arow + 64] = ra1.w;
    *reinterpret_cast<float4*>(&Bs[0][wk][wcol])     = rw0;
    *reinterpret_cast<float4*>(&Bs[0][wk + 8][wcol]) = rw1;
    __syncthreads();

    int st = 0;
    for (int k0 = GBK; k0 <= DD; k0 += GBK) {
        const bool more = (k0 < DD);
        if (more) {
            ra0 = *reinterpret_cast<const float4*>(A0 + k0);
            ra1 = *reinterpret_cast<const float4*>(A1 + k0);
            rw0 = *reinterpret_cast<const float4*>(&W[(size_t)(k0 + wk) * UU + wcol]);
            rw1 = *reinterpret_cast<const float4*>(&W[(size_t)(k0 + wk + 8) * UU + wcol]);
        }

        #pragma unroll
        for (int k = 0; k < GBK; k++) {
            float a[8], b[8];
            *reinterpret_cast<float4*>(&a[0]) =
                *reinterpret_cast<const float4*>(&As[st][k][ty * 8]);
            *reinterpret_cast<float4*>(&a[4]) =
                *reinterpret_cast<const float4*>(&As[st][k][ty * 8 + 4]);
            *reinterpret_cast<float4*>(&b[0]) =
                *reinterpret_cast<const float4*>(&Bs[st][k][tx * 8]);
            *reinterpret_cast<float4*>(&b[4]) =
                *reinterpret_cast<const float4*>(&Bs[st][k][tx * 8 + 4]);
            #pragma unroll
            for (int i = 0; i < 8; i++)
                #pragma unroll
                for (int j = 0; j < 8; j++)
                    acc[i][j] = fmaf(a[i], b[j], acc[i][j]);
        }

        if (more) {
            const int ns = st ^ 1;
            As[ns][ak + 0][arow] = ra0.x; As[ns][ak + 1][arow] = ra0.y;
            As[ns][ak + 2][arow] = ra0.z; As[ns][ak + 3][arow] = ra0.w;
            As[ns][ak + 0][arow + 64] = ra1.x; As[ns][ak + 1][arow + 64] = ra1.y;
            As[ns][ak + 2][arow + 64] = ra1.z; As[ns][ak + 3][arow + 64] = ra1.w;
            *reinterpret_cast<float4*>(&Bs[ns][wk][wcol])     = rw0;
            *reinterpret_cast<float4*>(&Bs[ns][wk + 8][wcol]) = rw1;
            __syncthreads();
            st = ns;
        }
    }

    float bv[8];
    *reinterpret_cast<float4*>(&bv[0]) =
        *reinterpret_cast<const float4*>(&bias[tx * 8]);
    *reinterpret_cast<float4*>(&bv[4]) =
        *reinterpret_cast<const float4*>(&bias[tx * 8 + 4]);

    #pragma unroll
    for (int i = 0; i < 8; i++) {
        const size_t row = (size_t)(row0 + ty * 8 + i);
        float4 o0, o1;
        o0.x = acc[i][0] + bv[0]; o0.y = acc[i][1] + bv[1];
        o0.z = acc[i][2] + bv[2]; o0.w = acc[i][3] + bv[3];
        o1.x = acc[i][4] + bv[4]; o1.y = acc[i][5] + bv[5];
        o1.z = acc[i][6] + bv[6]; o1.w = acc[i][7] + bv[7];
        *reinterpret_cast<float4*>(&g_logits[row * UU + tx * 8])     = o0;
        *reinterpret_cast<float4*>(&g_logits[row * UU + tx * 8 + 4]) = o1;
    }
}

// ---------------------------------------------------------------------------
// ordered-int argmax helpers (exact, first-index tie rule)
// ---------------------------------------------------------------------------
__device__ __forceinline__ unsigned fkey(float f)
{
    const unsigned b = __float_as_uint(f);
    return b ^ ((unsigned)(((int)b) >> 31) | 0x80000000u);
}
__device__ __forceinline__ unsigned redux_max_u32(unsigned v)
{
    unsigned r;
    asm("redux.sync.max.u32 %0, %1, 0xffffffff;" : "=r"(r) : "r"(v));
    return r;
}
__device__ __forceinline__ unsigned redux_min_u32(unsigned v)
{
    unsigned r;
    asm("redux.sync.min.u32 %0, %1, 0xffffffff;" : "=r"(r) : "r"(v));
    return r;
}

// packed fp32 add (Blackwell f32x2) + 3-input max (sm_90+ FMNMX3)
#define ADD2(d, a, b) \
    asm("add.rn.f32x2 %0, %1, %2;" : "=l"(d) : "l"(a), "l"(b))
#define UNPK2(lo, hi, v) \
    asm("mov.b64 {%0, %1}, %2;" : "=r"(lo), "=r"(hi) : "l"(v))
#define MAX3(d, a, b, c) \
    asm("max.f32 %0, %1, %2, %3;" : "=f"(d) : "f"(a), "f"(b), "f"(c))

// ---------------------------------------------------------------------------
// Kernel 2: Viterbi. One CTA/batch, 128 threads, thread = state u.
// Inner loop: 64 packed ADD2 + 64 MAX3 (each max3 folds one ADD2's pair into
// an accumulator). 8 accumulators, 4-op max3 tree. Broadcast LDS, one
// barrier/step, 4-register static prefetch ring.
// ---------------------------------------------------------------------------
#define CHT_LD 132   // 528B rows: 16B-aligned, de-striped STS

__global__ __launch_bounds__(128, 1)
void viterbi_kernel(const float* __restrict__ chain,
                    float* __restrict__ out)
{
    extern __shared__ float sm[];
    float* chT   = sm;                 // [128][CHT_LD]
    float* state = sm + UU * CHT_LD;   // [2][128]

    const int tid = threadIdx.x;       // = u, 0..127
    const int b   = blockIdx.x;
    const int u   = tid;

    const float* lg = g_logits + (size_t)b * TT * UU;
    float*       hb = g_hist   + (size_t)b * TT * UU;

    // Transposed chain into smem (backtrace)
    for (int i = tid; i < UU * UU; i += 128) {
        const int r = i >> 7, c = i & 127;
        chT[c * CHT_LD + r] = chain[i];
    }

    // full chain column for this u, packed: cpk[k] = (C[2k][u], C[2k+1][u])
    u64 cpk[64];
    #pragma unroll
    for (int k = 0; k < 64; k++) {
        const float c0 = chain[(size_t)(2 * k)     * UU + u];
        const float c1 = chain[(size_t)(2 * k + 1) * UU + u];
        asm("mov.b64 %0, {%1, %2};" : "=l"(cpk[k])
            : "r"(__float_as_uint(c0)), "r"(__float_as_uint(c1)));
    }

    state[tid] = lg[tid];

    // prefetch ring: p0..p3 hold logits rows t=1..4 for this u
    float p0 = lg[1 * UU + u];
    float p1 = lg[2 * UU + u];
    float p2 = lg[3 * UU + u];
    float p3 = lg[4 * UU + u];
    const float* pref_ptr = lg + (size_t)5 * UU + u;
    float*       hist_ptr = hb + (size_t)1 * UU + u;

    __syncthreads();

    int cur = 0;

#define VSTEP(T, PREG)                                                       \
    {                                                                        \
        const float pot = PREG;                                              \
        if ((T) + 4 < TT) PREG = *pref_ptr;                                  \
        pref_ptr += UU;                                                      \
        const float* stp = state + cur * UU;                                 \
        float m0 = -INFINITY, m1 = -INFINITY, m2 = -INFINITY,                \
              m3 = -INFINITY, m4 = -INFINITY, m5 = -INFINITY,                \
              m6 = -INFINITY, m7 = -INFINITY;                                \
        _Pragma("unroll")                                                    \
        for (int j = 0; j < 128; j += 16) {                                  \
            const ulonglong2 sA =                                            \
                *reinterpret_cast<const ulonglong2*>(&stp[j]);               \
            const ulonglong2 sB =                                            \
                *reinterpret_cast<const ulonglong2*>(&stp[j + 4]);           \
            const ulonglong2 sC =                                            \
                *reinterpret_cast<const ulonglong2*>(&stp[j + 8]);           \
            const ulonglong2 sD =                                            \
                *reinterpret_cast<const ulonglong2*>(&stp[j + 12]);          \
            u64 r0, r1, r2, r3, r4, r5, r6, r7;                              \
            ADD2(r0, sA.x, cpk[(j >> 1) + 0]);                               \
            ADD2(r1, sA.y, cpk[(j >> 1) + 1]);                               \
            ADD2(r2, sB.x, cpk[(j >> 1) + 2]);                               \
            ADD2(r3, sB.y, cpk[(j >> 1) + 3]);                               \
            ADD2(r4, sC.x, cpk[(j >> 1) + 4]);                               \
            ADD2(r5, sC.y, cpk[(j >> 1) + 5]);                               \
            ADD2(r6, sD.x, cpk[(j >> 1) + 6]);                               \
            ADD2(r7, sD.y, cpk[(j >> 1) + 7]);                               \
            unsigned x0, x1, x2, x3, x4, x5, x6, x7;                         \
            unsigned y0, y1, y2, y3, y4, y5, y6, y7;                         \
            UNPK2(x0, x1, r0);                                               \
            UNPK2(x2, x3, r1);                                               \
            UNPK2(x4, x5, r2);                                               \
            UNPK2(x6, x7, r3);                                               \
            UNPK2(y0, y1, r4);                                               \
            UNPK2(y2, y3, r5);                                               \
            UNPK2(y4, y5, r6);                                               \
            UNPK2(y6, y7, r7);                                               \
            MAX3(m0, m0, __uint_as_float(x0), __uint_as_float(x1));          \
            MAX3(m1, m1, __uint_as_float(x2), __uint_as_float(x3));          \
            MAX3(m2, m2, __uint_as_float(x4), __uint_as_float(x5));          \
            MAX3(m3, m3, __uint_as_float(x6), __uint_as_float(x7));          \
            MAX3(m4, m4, __uint_as_float(y0), __uint_as_float(y1));          \
            MAX3(m5, m5, __uint_as_float(y2), __uint_as_float(y3));          \
            MAX3(m6, m6, __uint_as_float(y4), __uint_as_float(y5));          \
            MAX3(m7, m7, __uint_as_float(y6), __uint_as_float(y7));          \
        }                                                                    \
        float t0, t1, t2, m;                                                 \
        MAX3(t0, m0, m1, m2);                                                \
        MAX3(t1, m3, m4, m5);                                                \
        MAX3(t2, m6, m7, t0);                                                \
        m = fmaxf(t1, t2);                                                   \
        const float ns = pot + m;                                            \
        state[(cur ^ 1) * UU + u] = ns;                                      \
        *hist_ptr = ns;                                                      \
        hist_ptr += UU;                                                      \
        cur ^= 1;                                                            \
        __syncthreads();                                                     \
    }

    int t = 1;
    for (; t + 3 < TT; t += 4) {
        VSTEP(t + 0, p0);
        VSTEP(t + 1, p1);
        VSTEP(t + 2, p2);
        VSTEP(t + 3, p3);
    }
    // tail: t = 509, 510, 511
    VSTEP(t + 0, p0);
    VSTEP(t + 1, p1);
    VSTEP(t + 2, p2);
#undef VSTEP

    // ---------------- Backtrace: warp 0 only ----------------
    if (tid < 32) {
        const int lane = tid;
        float* o = out + (size_t)b * TT;

        const float4 fs =
            *reinterpret_cast<const float4*>(&state[cur * UU + lane * 4]);
        unsigned k0 = fkey(fs.x), k1 = fkey(fs.y);
        unsigned k2 = fkey(fs.z), k3 = fkey(fs.w);
        unsigned M = redux_max_u32(umax(umax(k0, k1), umax(k2, k3)));
        unsigned idx = 0x7fffffffu;
        if (k3 == M) idx = lane * 4 + 3;
        if (k2 == M) idx = lane * 4 + 2;
        if (k1 == M) idx = lane * 4 + 1;
        if (k0 == M) idx = lane * 4 + 0;
        unsigned tag = redux_min_u32(idx);
        if (lane == 0) o[TT - 1] = (float)tag;

        const float* row_next = hb + (size_t)(TT - 2) * UU;
        float4 sb = *reinterpret_cast<const float4*>(&row_next[lane * 4]);
        for (int tt = TT - 2; tt >= 0; tt--) {
            const float4 sv = sb;
            if (tt > 0) {
                const float* rp =
                    (tt - 1 == 0) ? lg : hb + (size_t)(tt - 1) * UU;
                sb = *reinterpret_cast<const float4*>(&rp[lane * 4]);
            }
            const float4 ch = *reinterpret_cast<const float4*>(
                &chT[tag * CHT_LD + lane * 4]);
            k0 = fkey(sv.x + ch.x);
            k1 = fkey(sv.y + ch.y);
            k2 = fkey(sv.z + ch.z);
            k3 = fkey(sv.w + ch.w);
            M = redux_max_u32(umax(umax(k0, k1), umax(k2, k3)));
            idx = 0x7fffffffu;
            if (k3 == M) idx = lane * 4 + 3;
            if (k2 == M) idx = lane * 4 + 2;
            if (k1 == M) idx = lane * 4 + 1;
            if (k0 == M) idx = lane * 4 + 0;
            tag = redux_min_u32(idx);
            if (lane == 0) o[tt] = (float)tag;
        }
    }
}

// ---------------------------------------------------------------------------
extern "C" void kernel_launch(void* const* d_in, const int* in_sizes, int n_in,
                              void* d_out, int out_size)
{
    const float* inputs = (const float*)d_in[0];   // (B,T,D)
    const float* kernel = (const float*)d_in[1];   // (D,U)
    const float* bias   = (const float*)d_in[2];   // (U)
    const float* chain  = (const float*)d_in[3];   // (U,U)
    float* out = (float*)d_out;                    // (B,T)

    (void)in_sizes; (void)n_in; (void)out_size;

    gemm_bias_kernel<<<MM / GBM, 256>>>(inputs, kernel, bias);

    const int smem_v = (UU * CHT_LD + 2 * UU) * (int)sizeof(float); // 68608
    cudaFuncSetAttribute(viterbi_kernel,
                         cudaFuncAttributeMaxDynamicSharedMemorySize,
                         smem_v);
    viterbi_kernel<<<BB, 128, smem_v>>>(chain, out);
}